// round 1
// baseline (speedup 1.0000x reference)
#include <cuda_runtime.h>

// Compact u table: only cols 0..3 of u are needed by the edge kernel.
// 65536 * 16B = 1 MB device-global scratch (N_NODES = 50000).
__device__ float4 g_u4[65536];

__device__ __forceinline__ void softmax3(float a, float b, float c,
                                         float& p0, float& p1, float& p2) {
    float m  = fmaxf(a, fmaxf(b, c));
    float e0 = __expf(a - m);
    float e1 = __expf(b - m);
    float e2 = __expf(c - m);
    float inv = __fdividef(1.0f, e0 + e1 + e2);
    p0 = e0 * inv;
    p1 = e1 * inv;
    p2 = e2 * inv;
}

// Kernel A: u = unary + KE(unary, U_IDX=[0..11 grouped by 3], signs=[-1,1,1], wu)
// Writes full u rows to out_u and compact first-4-cols to g_u4.
__global__ void kenn_node_kernel(const float* __restrict__ unary,
                                 const float* __restrict__ wu,
                                 float* __restrict__ out_u,
                                 int n_nodes) {
    int i = blockIdx.x * blockDim.x + threadIdx.x;
    if (i >= n_nodes) return;

    const float4* in4 = reinterpret_cast<const float4*>(unary) + (size_t)i * 4;
    float x[16];
    reinterpret_cast<float4*>(x)[0] = in4[0];
    reinterpret_cast<float4*>(x)[1] = in4[1];
    reinterpret_cast<float4*>(x)[2] = in4[2];
    reinterpret_cast<float4*>(x)[3] = in4[3];

    float u[16];
#pragma unroll
    for (int c = 0; c < 4; c++) {
        float w = wu[c];
        float p0, p1, p2;
        softmax3(-x[3*c], x[3*c+1], x[3*c+2], p0, p1, p2);
        u[3*c]     = x[3*c]     - w * p0;   // sign -1
        u[3*c + 1] = x[3*c + 1] + w * p1;   // sign +1
        u[3*c + 2] = x[3*c + 2] + w * p2;   // sign +1
    }
#pragma unroll
    for (int k = 12; k < 16; k++) u[k] = x[k];

    float4* o4 = reinterpret_cast<float4*>(out_u) + (size_t)i * 4;
    o4[0] = reinterpret_cast<float4*>(u)[0];
    o4[1] = reinterpret_cast<float4*>(u)[1];
    o4[2] = reinterpret_cast<float4*>(u)[2];
    o4[3] = reinterpret_cast<float4*>(u)[3];

    g_u4[i] = make_float4(u[0], u[1], u[2], u[3]);
}

// Kernel B: per-edge clause c over (u[i1][c], u[i2][c], binary[e][c]),
// signs [-1,1,1], weight wb[c]. Scatter-add node deltas into out_u (atomics),
// write binary + delta directly.
__global__ void kenn_edge_kernel(const float4* __restrict__ binary,
                                 const float* __restrict__ wb,
                                 const int* __restrict__ e1,
                                 const int* __restrict__ e2,
                                 float* __restrict__ out_u,
                                 float4* __restrict__ out_b,
                                 int n_edges) {
    int e = blockIdx.x * blockDim.x + threadIdx.x;
    if (e >= n_edges) return;

    int a = e1[e];
    int b = e2[e];

    float4 ua4 = g_u4[a];
    float4 ub4 = g_u4[b];
    float4 bv4 = binary[e];

    float ua[4] = {ua4.x, ua4.y, ua4.z, ua4.w};
    float ub[4] = {ub4.x, ub4.y, ub4.z, ub4.w};
    float bv[4] = {bv4.x, bv4.y, bv4.z, bv4.w};
    float bo[4];

    float* oua = out_u + (size_t)a * 16;
    float* oub = out_u + (size_t)b * 16;

#pragma unroll
    for (int c = 0; c < 4; c++) {
        float w = wb[c];
        float p0, p1, p2;
        softmax3(-ua[c], ub[c], bv[c], p0, p1, p2);
        atomicAdd(oua + c, -w * p0);   // delta to u[i1][c], sign -1
        atomicAdd(oub + c,  w * p1);   // delta to u[i2][c], sign +1
        bo[c] = bv[c] + w * p2;        // binary delta, sign +1
    }

    out_b[e] = make_float4(bo[0], bo[1], bo[2], bo[3]);
}

extern "C" void kernel_launch(void* const* d_in, const int* in_sizes, int n_in,
                              void* d_out, int out_size) {
    const float* unary  = (const float*)d_in[0];
    const float* binary = (const float*)d_in[1];
    const float* wu     = (const float*)d_in[2];
    const float* wb     = (const float*)d_in[3];
    const int*   eidx   = (const int*)d_in[4];

    int n_nodes = in_sizes[0] / 16;
    int n_edges = in_sizes[1] / 4;

    float*  out_u = (float*)d_out;
    float4* out_b = (float4*)((float*)d_out + (size_t)n_nodes * 16);

    int tb = 256;
    kenn_node_kernel<<<(n_nodes + tb - 1) / tb, tb>>>(unary, wu, out_u, n_nodes);
    kenn_edge_kernel<<<(n_edges + tb - 1) / tb, tb>>>(
        (const float4*)binary, wb, eidx, eidx + n_edges, out_u, out_b, n_edges);
}

// round 2
// speedup vs baseline: 2.1203x; 2.1203x over previous
#include <cuda_runtime.h>

// Compact u table: only cols 0..3 of u are needed by the edge kernel.
// 65536 * 16B = 1 MB device-global scratch (N_NODES = 50000), L2-resident.
__device__ float4 g_u4[65536];

__device__ __forceinline__ void softmax3(float a, float b, float c,
                                         float& p0, float& p1, float& p2) {
    float m  = fmaxf(a, fmaxf(b, c));
    float e0 = __expf(a - m);
    float e1 = __expf(b - m);
    float e2 = __expf(c - m);
    float inv = __fdividef(1.0f, e0 + e1 + e2);
    p0 = e0 * inv;
    p1 = e1 * inv;
    p2 = e2 * inv;
}

// Vector reduction: one REDG.128 instead of four REDG.32.
__device__ __forceinline__ void red_add_v4(float* addr, float a, float b,
                                           float c, float d) {
    asm volatile("red.global.add.v4.f32 [%0], {%1, %2, %3, %4};"
                 :: "l"(addr), "f"(a), "f"(b), "f"(c), "f"(d)
                 : "memory");
}

// Kernel A: u = unary + KE(unary, U_IDX grouped by 3, signs=[-1,1,1], wu)
__global__ void kenn_node_kernel(const float* __restrict__ unary,
                                 const float* __restrict__ wu,
                                 float* __restrict__ out_u,
                                 int n_nodes) {
    int i = blockIdx.x * blockDim.x + threadIdx.x;
    if (i >= n_nodes) return;

    const float4* in4 = reinterpret_cast<const float4*>(unary) + (size_t)i * 4;
    float x[16];
    reinterpret_cast<float4*>(x)[0] = in4[0];
    reinterpret_cast<float4*>(x)[1] = in4[1];
    reinterpret_cast<float4*>(x)[2] = in4[2];
    reinterpret_cast<float4*>(x)[3] = in4[3];

    float u[16];
#pragma unroll
    for (int c = 0; c < 4; c++) {
        float w = wu[c];
        float p0, p1, p2;
        softmax3(-x[3*c], x[3*c+1], x[3*c+2], p0, p1, p2);
        u[3*c]     = x[3*c]     - w * p0;   // sign -1
        u[3*c + 1] = x[3*c + 1] + w * p1;   // sign +1
        u[3*c + 2] = x[3*c + 2] + w * p2;   // sign +1
    }
#pragma unroll
    for (int k = 12; k < 16; k++) u[k] = x[k];

    float4* o4 = reinterpret_cast<float4*>(out_u) + (size_t)i * 4;
    o4[0] = reinterpret_cast<float4*>(u)[0];
    o4[1] = reinterpret_cast<float4*>(u)[1];
    o4[2] = reinterpret_cast<float4*>(u)[2];
    o4[3] = reinterpret_cast<float4*>(u)[3];

    g_u4[i] = make_float4(u[0], u[1], u[2], u[3]);
}

// Kernel B: per-edge clause c over (u[i1][c], u[i2][c], binary[e][c]),
// signs [-1,1,1], weight wb[c]. Deltas to i1 and i2 each hit 4 contiguous
// floats (row cols 0..3) -> two vector reductions per edge.
__global__ void kenn_edge_kernel(const float4* __restrict__ binary,
                                 const float* __restrict__ wb,
                                 const int* __restrict__ e1,
                                 const int* __restrict__ e2,
                                 float* __restrict__ out_u,
                                 float4* __restrict__ out_b,
                                 int n_edges) {
    int e = blockIdx.x * blockDim.x + threadIdx.x;
    if (e >= n_edges) return;

    int a = e1[e];
    int b = e2[e];

    float4 ua4 = __ldg(&g_u4[a]);
    float4 ub4 = __ldg(&g_u4[b]);
    float4 bv4 = binary[e];

    float ua[4] = {ua4.x, ua4.y, ua4.z, ua4.w};
    float ub[4] = {ub4.x, ub4.y, ub4.z, ub4.w};
    float bv[4] = {bv4.x, bv4.y, bv4.z, bv4.w};
    float d1[4], d2[4], bo[4];

#pragma unroll
    for (int c = 0; c < 4; c++) {
        float w = wb[c];
        float p0, p1, p2;
        softmax3(-ua[c], ub[c], bv[c], p0, p1, p2);
        d1[c] = -w * p0;          // delta to u[i1][c], sign -1
        d2[c] =  w * p1;          // delta to u[i2][c], sign +1
        bo[c] = bv[c] + w * p2;   // binary delta, sign +1
    }

    red_add_v4(out_u + (size_t)a * 16, d1[0], d1[1], d1[2], d1[3]);
    red_add_v4(out_u + (size_t)b * 16, d2[0], d2[1], d2[2], d2[3]);

    out_b[e] = make_float4(bo[0], bo[1], bo[2], bo[3]);
}

extern "C" void kernel_launch(void* const* d_in, const int* in_sizes, int n_in,
                              void* d_out, int out_size) {
    const float* unary  = (const float*)d_in[0];
    const float* binary = (const float*)d_in[1];
    const float* wu     = (const float*)d_in[2];
    const float* wb     = (const float*)d_in[3];
    const int*   eidx   = (const int*)d_in[4];

    int n_nodes = in_sizes[0] / 16;
    int n_edges = in_sizes[1] / 4;

    float*  out_u = (float*)d_out;
    float4* out_b = (float4*)((float*)d_out + (size_t)n_nodes * 16);

    int tb = 256;
    kenn_node_kernel<<<(n_nodes + tb - 1) / tb, tb>>>(unary, wu, out_u, n_nodes);
    kenn_edge_kernel<<<(n_edges + tb - 1) / tb, tb>>>(
        (const float4*)binary, wb, eidx, eidx + n_edges, out_u, out_b, n_edges);
}